// round 12
// baseline (speedup 1.0000x reference)
#include <cuda_runtime.h>
#include <math.h>

// Problem constants (fixed shapes)
#define B_ROWS  4096
#define N_NODES 2048
#define N_IN    512
#define N_OUT   256
#define CHUNK   128
#define NCHUNK  12
#define KSPLIT  8

// Persistent scratch (transposed layouts)
__device__ float g_out_T[(size_t)N_NODES * B_ROWS];           // [node][row], 32 MB
__device__ float g_zp[(size_t)KSPLIT * CHUNK * B_ROWS];       // [split][node][row], 16 MB

typedef unsigned long long u64;

__device__ __forceinline__ u64 pack2(float x, float y) {
    u64 r; asm("mov.b64 %0, {%1,%2};" : "=l"(r) : "f"(x), "f"(y)); return r;
}
__device__ __forceinline__ void ffma2(u64& d, u64 a, u64 b) {
    asm("fma.rn.f32x2 %0, %1, %2, %0;" : "+l"(d) : "l"(a), "l"(b));
}
__device__ __forceinline__ float2 unpack2(u64 v) {
    float2 f; asm("mov.b64 {%0,%1}, %2;" : "=f"(f.x), "=f"(f.y) : "l"(v)); return f;
}
// sigmoid(clip(5z, -60, 60)) == 1/(1 + exp2(clamp(-7.2134752*z, +-86.5617)))
__device__ __forceinline__ float sig5(float z) {
    float u = fminf(fmaxf(-7.2134752f * z, -86.5617f), 86.5617f);
    float e; asm("ex2.approx.f32 %0, %1;" : "=f"(e) : "f"(u));
    float r; asm("rcp.approx.f32 %0, %1;" : "=f"(r) : "f"(1.0f + e));
    return r;
}

// ---------------------------------------------------------------------------
// GEMM: g_zp[ks][node][row] = g_out_T[k, row] @ W[i0+node][k] over k-split ks.
// BM=128, BN=128, BK=16, 256 threads, grid = (32 rowblocks, 8 ksplits).
// (unchanged from R9 — measured 31us avg)
// ---------------------------------------------------------------------------
#define BM    128
#define BKt   16
#define ASTR  132     // floats per k-row
#define BSTRU 132     // u64 per k-row

__global__ __launch_bounds__(256, 2) void gemm_chunk(const float* __restrict__ W,
                                                     int i0)
{
    const int P     = N_IN + i0;
    const int kq    = P / KSPLIT;          // multiple of 16
    const int k0    = blockIdx.y * kq;
    const int nIter = kq / BKt;

    __shared__ float As[2][BKt * ASTR];
    __shared__ u64   Bs[2][BKt * BSTRU];

    const int tid  = threadIdx.x;
    const int brow = blockIdx.x * BM;
    const int warp = tid >> 5;
    const int lane = tid & 31;
    const int wr   = warp >> 1;            // 0..3
    const int wc   = warp & 1;             // 0..1
    const int lr   = lane >> 3;            // 0..3
    const int lc   = lane & 7;             // 0..7
    const int r0   = 32 * wr + 8 * lr;     // thread rows r0..r0+7
    const int cb   = 64 * wc + 2 * lc;     // cols = cb + 16*j + {0,1}

    const int kload = tid >> 4;            // 0..15
    const int mld   = (tid & 15) * 8;      // 0..120
    const int bc    = tid >> 1;            // 0..127
    const int bk    = (tid & 1) * 8;       // 0,8

    const size_t stepA = (size_t)BKt * B_ROWS;
    const float* Ag = g_out_T + (size_t)(k0 + kload) * B_ROWS + brow + mld;
    const float* Bg = W + (size_t)(i0 + bc) * N_NODES + k0 + bk;

    u64 acc[4][8];
#pragma unroll
    for (int p = 0; p < 4; p++)
#pragma unroll
        for (int j = 0; j < 8; j++) acc[p][j] = 0ULL;

    // preload tile 0
    {
        float4 a0 = *(const float4*)Ag;
        float4 a1 = *(const float4*)(Ag + 4);
        *(float4*)&As[0][kload * ASTR + mld]     = a0;
        *(float4*)&As[0][kload * ASTR + mld + 4] = a1;
        float4 b0 = *(const float4*)Bg;
        float4 b1 = *(const float4*)(Bg + 4);
        Bs[0][(bk + 0) * BSTRU + bc] = pack2(b0.x, b0.x);
        Bs[0][(bk + 1) * BSTRU + bc] = pack2(b0.y, b0.y);
        Bs[0][(bk + 2) * BSTRU + bc] = pack2(b0.z, b0.z);
        Bs[0][(bk + 3) * BSTRU + bc] = pack2(b0.w, b0.w);
        Bs[0][(bk + 4) * BSTRU + bc] = pack2(b1.x, b1.x);
        Bs[0][(bk + 5) * BSTRU + bc] = pack2(b1.y, b1.y);
        Bs[0][(bk + 6) * BSTRU + bc] = pack2(b1.z, b1.z);
        Bs[0][(bk + 7) * BSTRU + bc] = pack2(b1.w, b1.w);
    }
    __syncthreads();

    int buf = 0;
    for (int it = 0; it < nIter; it++) {
        const bool more = (it + 1 < nIter);
        float4 a0v, a1v, b0v, b1v;
        if (more) {
            const float* Ag2 = Ag + (size_t)(it + 1) * stepA;
            const float* Bg2 = Bg + (it + 1) * BKt;
            a0v = *(const float4*)Ag2;
            a1v = *(const float4*)(Ag2 + 4);
            b0v = *(const float4*)Bg2;
            b1v = *(const float4*)(Bg2 + 4);
        }

#pragma unroll
        for (int kk = 0; kk < BKt; kk++) {
            ulonglong2 aA = *(const ulonglong2*)&As[buf][kk * ASTR + r0];
            ulonglong2 aB = *(const ulonglong2*)&As[buf][kk * ASTR + r0 + 4];
            ulonglong2 bq0 = *(const ulonglong2*)&Bs[buf][kk * BSTRU + cb];
            ulonglong2 bq1 = *(const ulonglong2*)&Bs[buf][kk * BSTRU + cb + 16];
            ulonglong2 bq2 = *(const ulonglong2*)&Bs[buf][kk * BSTRU + cb + 32];
            ulonglong2 bq3 = *(const ulonglong2*)&Bs[buf][kk * BSTRU + cb + 48];
            ffma2(acc[0][0], aA.x, bq0.x); ffma2(acc[0][1], aA.x, bq0.y);
            ffma2(acc[1][0], aA.y, bq0.x); ffma2(acc[1][1], aA.y, bq0.y);
            ffma2(acc[2][0], aB.x, bq0.x); ffma2(acc[2][1], aB.x, bq0.y);
            ffma2(acc[3][0], aB.y, bq0.x); ffma2(acc[3][1], aB.y, bq0.y);
            ffma2(acc[0][2], aA.x, bq1.x); ffma2(acc[0][3], aA.x, bq1.y);
            ffma2(acc[1][2], aA.y, bq1.x); ffma2(acc[1][3], aA.y, bq1.y);
            ffma2(acc[2][2], aB.x, bq1.x); ffma2(acc[2][3], aB.x, bq1.y);
            ffma2(acc[3][2], aB.y, bq1.x); ffma2(acc[3][3], aB.y, bq1.y);
            ffma2(acc[0][4], aA.x, bq2.x); ffma2(acc[0][5], aA.x, bq2.y);
            ffma2(acc[1][4], aA.y, bq2.x); ffma2(acc[1][5], aA.y, bq2.y);
            ffma2(acc[2][4], aB.x, bq2.x); ffma2(acc[2][5], aB.x, bq2.y);
            ffma2(acc[3][4], aB.y, bq2.x); ffma2(acc[3][5], aB.y, bq2.y);
            ffma2(acc[0][6], aA.x, bq3.x); ffma2(acc[0][7], aA.x, bq3.y);
            ffma2(acc[1][6], aA.y, bq3.x); ffma2(acc[1][7], aA.y, bq3.y);
            ffma2(acc[2][6], aB.x, bq3.x); ffma2(acc[2][7], aB.x, bq3.y);
            ffma2(acc[3][6], aB.y, bq3.x); ffma2(acc[3][7], aB.y, bq3.y);
        }

        if (more) {
            const int nb = buf ^ 1;
            *(float4*)&As[nb][kload * ASTR + mld]     = a0v;
            *(float4*)&As[nb][kload * ASTR + mld + 4] = a1v;
            Bs[nb][(bk + 0) * BSTRU + bc] = pack2(b0v.x, b0v.x);
            Bs[nb][(bk + 1) * BSTRU + bc] = pack2(b0v.y, b0v.y);
            Bs[nb][(bk + 2) * BSTRU + bc] = pack2(b0v.z, b0v.z);
            Bs[nb][(bk + 3) * BSTRU + bc] = pack2(b0v.w, b0v.w);
            Bs[nb][(bk + 4) * BSTRU + bc] = pack2(b1v.x, b1v.x);
            Bs[nb][(bk + 5) * BSTRU + bc] = pack2(b1v.y, b1v.y);
            Bs[nb][(bk + 6) * BSTRU + bc] = pack2(b1v.z, b1v.z);
            Bs[nb][(bk + 7) * BSTRU + bc] = pack2(b1v.w, b1v.w);
        }
        __syncthreads();
        buf ^= 1;
    }

    float* zbase = g_zp + (size_t)blockIdx.y * CHUNK * B_ROWS;
#pragma unroll
    for (int p = 0; p < 4; p++) {
#pragma unroll
        for (int j = 0; j < 4; j++) {
#pragma unroll
            for (int h = 0; h < 2; h++) {
                const int c = cb + 16 * j + h;
                *(u64*)(zbase + (size_t)c * B_ROWS + brow + r0 + 2 * p) =
                    acc[p][2 * j + h];
            }
        }
    }
}

// ---------------------------------------------------------------------------
// Triangular epilogue v3: warp-specialized pipeline, single-copy code.
// Block = 8 warps x 32 lanes; all warps share rows [32b, 32b+32); warp w owns
// node sub-chunk w (16 nodes). Lane = batch row (no shuffles, per-lane MUFU).
// Round j (NOT unrolled -> one code copy, small I$ footprint): barrier; warps
// w>=j add rank-16 dense update from sub-chunk j-1; warp j runs the 16-step
// serial phase. All dense W tiles L2-prefetched at start; serial W tiles in smem.
// ---------------------------------------------------------------------------
__global__ __launch_bounds__(256) void epi_chunk(const float* __restrict__ W,
                                                 const float* __restrict__ bias,
                                                 int i0)
{
    __shared__ u64   o_sm[64 * 32];        // [node pair][lane], 16 KB
    __shared__ float Wt[8][16][16];        // per-warp serial W tile, 4 KB

    const int P    = N_IN + i0;
    const int tid  = threadIdx.x;
    const int w    = tid >> 5;
    const int lane = tid & 31;
    const int m    = blockIdx.x * 32 + lane;
    const int nb   = 16 * w;

    // ---- stage this warp's 16x16 serial W tile into smem (off crit path)
#pragma unroll
    for (int i = lane; i < 64; i += 32) {
        const int row = i >> 2, c4 = i & 3;
        float4 v = *(const float4*)&W[(size_t)(i0 + nb + row) * N_NODES + P + nb + 4 * c4];
        *(float4*)&Wt[w][row][4 * c4] = v;
    }
    // ---- prefetch ALL dense W tiles this warp will need (rounds 1..w) to L2
    {
        const int row = lane & 15, half = lane >> 4;
#pragma unroll 1
        for (int j = 0; j < w; j++) {
            const float* pf = &W[(size_t)(i0 + nb + row) * N_NODES + P + 16 * j + 8 * half];
            asm volatile("prefetch.global.L2 [%0];" :: "l"(pf));
        }
    }
    __syncwarp();

    // ---- fold GEMM k-split partials + bias into register acc
    float acc16[16];
#pragma unroll
    for (int n = 0; n < 16; n++) {
        float v = bias[i0 + nb + n];
#pragma unroll
        for (int s = 0; s < KSPLIT; s++)
            v += g_zp[((size_t)s * CHUNK + nb + n) * B_ROWS + m];
        acc16[n] = v;
    }

    // ---- pipelined rounds (single code copy)
#pragma unroll 1
    for (int j = 0; j < 8; j++) {
        if (j > 0) {
            __syncthreads();
            if (w >= j) {
                u64 o8[8];
#pragma unroll
                for (int t = 0; t < 8; t++)
                    o8[t] = o_sm[(8 * (j - 1) + t) * 32 + lane];
#pragma unroll
                for (int n = 0; n < 16; n++) {
                    const float* wr = W + (size_t)(i0 + nb + n) * N_NODES + P + 16 * (j - 1);
                    ulonglong2 w01 = *(const ulonglong2*)wr;
                    ulonglong2 w23 = *(const ulonglong2*)(wr + 4);
                    ulonglong2 w45 = *(const ulonglong2*)(wr + 8);
                    ulonglong2 w67 = *(const ulonglong2*)(wr + 12);
                    u64 zp = 0ULL;
                    ffma2(zp, w01.x, o8[0]); ffma2(zp, w01.y, o8[1]);
                    ffma2(zp, w23.x, o8[2]); ffma2(zp, w23.y, o8[3]);
                    ffma2(zp, w45.x, o8[4]); ffma2(zp, w45.y, o8[5]);
                    ffma2(zp, w67.x, o8[6]); ffma2(zp, w67.y, o8[7]);
                    float2 f = unpack2(zp);
                    acc16[n] += f.x + f.y;
                }
            }
        }
        if (w == j) {
            // serial phase: 16 nodes, fully unrolled, W from smem tile
            float o_loc[16];
            u64 op_loc[8];
#pragma unroll
            for (int cc = 0; cc < 16; cc++) {
                const float* wr = &Wt[w][cc][0];
                float z = acc16[cc];
                if (cc >= 2) {
                    u64 zp2 = 0ULL;
#pragma unroll
                    for (int jj = 0; jj < (cc >> 1); jj++)
                        ffma2(zp2, *(const u64*)(wr + 2 * jj), op_loc[jj]);
                    float2 f = unpack2(zp2);
                    z += f.x + f.y;
                }
                if (cc & 1)
                    z += wr[cc - 1] * o_loc[cc - 1];
                float o = sig5(z);
                o_loc[cc] = o;
                g_out_T[(size_t)(P + nb + cc) * B_ROWS + m] = o;
                if (cc & 1) {
                    op_loc[cc >> 1] = pack2(o_loc[cc - 1], o);
                    o_sm[(8 * w + (cc >> 1)) * 32 + lane] = op_loc[cc >> 1];
                }
            }
        }
    }
}

// ---------------------------------------------------------------------------
// Transpose kernels (32x32 smem tiles)
// ---------------------------------------------------------------------------
__global__ void init_T(const float* __restrict__ x)
{
    __shared__ float t[32][33];
    const int rb = blockIdx.x * 32;
    const int cb = blockIdx.y * 32;
    const int tx = threadIdx.x, ty = threadIdx.y;
#pragma unroll
    for (int j = 0; j < 4; j++)
        t[ty + 8 * j][tx] = x[(size_t)(rb + ty + 8 * j) * N_IN + cb + tx];
    __syncthreads();
#pragma unroll
    for (int j = 0; j < 4; j++)
        g_out_T[(size_t)(cb + ty + 8 * j) * B_ROWS + rb + tx] = t[tx][ty + 8 * j];
}

__global__ void copy_T(float* __restrict__ out)
{
    __shared__ float t[32][33];
    const int rb = blockIdx.x * 32;
    const int cb = blockIdx.y * 32;
    const int tx = threadIdx.x, ty = threadIdx.y;
#pragma unroll
    for (int j = 0; j < 4; j++)
        t[ty + 8 * j][tx] = g_out_T[(size_t)(N_NODES - N_OUT + cb + ty + 8 * j) * B_ROWS
                                    + rb + tx];
    __syncthreads();
#pragma unroll
    for (int j = 0; j < 4; j++)
        out[(size_t)(rb + ty + 8 * j) * N_OUT + cb + tx] = t[tx][ty + 8 * j];
}

// ---------------------------------------------------------------------------
extern "C" void kernel_launch(void* const* d_in, const int* in_sizes, int n_in,
                              void* d_out, int out_size)
{
    (void)in_sizes; (void)n_in; (void)out_size;
    const float* x  = (const float*)d_in[0];
    const float* W  = (const float*)d_in[1];
    const float* b  = (const float*)d_in[2];
    float* out = (float*)d_out;

    dim3 tblk(32, 8);
    init_T<<<dim3(B_ROWS / 32, N_IN / 32), tblk>>>(x);
    for (int k = 0; k < NCHUNK; k++) {
        gemm_chunk<<<dim3(B_ROWS / BM, KSPLIT), 256>>>(W, k * CHUNK);
        epi_chunk<<<B_ROWS / 32, 256>>>(W, b, k * CHUNK);
    }
    copy_T<<<dim3(B_ROWS / 32, N_OUT / 32), tblk>>>(out);
}

// round 13
// speedup vs baseline: 1.2266x; 1.2266x over previous
#include <cuda_runtime.h>
#include <math.h>

// Problem constants (fixed shapes)
#define B_ROWS  4096
#define N_NODES 2048
#define N_IN    512
#define N_OUT   256
#define CHUNK   128
#define NCHUNK  12
#define KSPLIT  8

// Persistent scratch (transposed layouts)
__device__ float g_out_T[(size_t)N_NODES * B_ROWS];           // [node][row], 32 MB
__device__ float g_zp[(size_t)KSPLIT * CHUNK * B_ROWS];       // [split][node][row], 16 MB

typedef unsigned long long u64;

__device__ __forceinline__ u64 pack2(float x, float y) {
    u64 r; asm("mov.b64 %0, {%1,%2};" : "=l"(r) : "f"(x), "f"(y)); return r;
}
__device__ __forceinline__ void ffma2(u64& d, u64 a, u64 b) {
    asm("fma.rn.f32x2 %0, %1, %2, %0;" : "+l"(d) : "l"(a), "l"(b));
}
__device__ __forceinline__ float2 unpack2(u64 v) {
    float2 f; asm("mov.b64 {%0,%1}, %2;" : "=f"(f.x), "=f"(f.y) : "l"(v)); return f;
}
// sigmoid(clip(5z,-60,60)) ~= 1/(1 + exp2(-7.2134752*z)); ex2 saturates to
// 0/inf and rcp(inf)=0, so the clamp is unnecessary (diff < 9e-27).
__device__ __forceinline__ float sig5(float z) {
    float u = -7.2134752f * z;
    float e; asm("ex2.approx.f32 %0, %1;" : "=f"(e) : "f"(u));
    float d = 1.0f + e;
    float r; asm("rcp.approx.f32 %0, %1;" : "=f"(r) : "f"(d));
    return r;
}

// ---------------------------------------------------------------------------
// GEMM: g_zp[ks][node][row] = g_out_T[k, row] @ W[i0+node][k] over k-split ks.
// BM=128, BN=128, BK=16, 256 threads, grid = (32 rowblocks, 8 ksplits).
// (unchanged — measured 31us @ P=768)
// ---------------------------------------------------------------------------
#define BM    128
#define BKt   16
#define ASTR  132     // floats per k-row
#define BSTRU 132     // u64 per k-row

__global__ __launch_bounds__(256, 2) void gemm_chunk(const float* __restrict__ W,
                                                     int i0)
{
    const int P     = N_IN + i0;
    const int kq    = P / KSPLIT;          // multiple of 16
    const int k0    = blockIdx.y * kq;
    const int nIter = kq / BKt;

    __shared__ float As[2][BKt * ASTR];
    __shared__ u64   Bs[2][BKt * BSTRU];

    const int tid  = threadIdx.x;
    const int brow = blockIdx.x * BM;
    const int warp = tid >> 5;
    const int lane = tid & 31;
    const int wr   = warp >> 1;            // 0..3
    const int wc   = warp & 1;             // 0..1
    const int lr   = lane >> 3;            // 0..3
    const int lc   = lane & 7;             // 0..7
    const int r0   = 32 * wr + 8 * lr;     // thread rows r0..r0+7
    const int cb   = 64 * wc + 2 * lc;     // cols = cb + 16*j + {0,1}

    const int kload = tid >> 4;            // 0..15
    const int mld   = (tid & 15) * 8;      // 0..120
    const int bc    = tid >> 1;            // 0..127
    const int bk    = (tid & 1) * 8;       // 0,8

    const size_t stepA = (size_t)BKt * B_ROWS;
    const float* Ag = g_out_T + (size_t)(k0 + kload) * B_ROWS + brow + mld;
    const float* Bg = W + (size_t)(i0 + bc) * N_NODES + k0 + bk;

    u64 acc[4][8];
#pragma unroll
    for (int p = 0; p < 4; p++)
#pragma unroll
        for (int j = 0; j < 8; j++) acc[p][j] = 0ULL;

    // preload tile 0
    {
        float4 a0 = *(const float4*)Ag;
        float4 a1 = *(const float4*)(Ag + 4);
        *(float4*)&As[0][kload * ASTR + mld]     = a0;
        *(float4*)&As[0][kload * ASTR + mld + 4] = a1;
        float4 b0 = *(const float4*)Bg;
        float4 b1 = *(const float4*)(Bg + 4);
        Bs[0][(bk + 0) * BSTRU + bc] = pack2(b0.x, b0.x);
        Bs[0][(bk + 1) * BSTRU + bc] = pack2(b0.y, b0.y);
        Bs[0][(bk + 2) * BSTRU + bc] = pack2(b0.z, b0.z);
        Bs[0][(bk + 3) * BSTRU + bc] = pack2(b0.w, b0.w);
        Bs[0][(bk + 4) * BSTRU + bc] = pack2(b1.x, b1.x);
        Bs[0][(bk + 5) * BSTRU + bc] = pack2(b1.y, b1.y);
        Bs[0][(bk + 6) * BSTRU + bc] = pack2(b1.z, b1.z);
        Bs[0][(bk + 7) * BSTRU + bc] = pack2(b1.w, b1.w);
    }
    __syncthreads();

    int buf = 0;
    for (int it = 0; it < nIter; it++) {
        const bool more = (it + 1 < nIter);
        float4 a0v, a1v, b0v, b1v;
        if (more) {
            const float* Ag2 = Ag + (size_t)(it + 1) * stepA;
            const float* Bg2 = Bg + (it + 1) * BKt;
            a0v = *(const float4*)Ag2;
            a1v = *(const float4*)(Ag2 + 4);
            b0v = *(const float4*)Bg2;
            b1v = *(const float4*)(Bg2 + 4);
        }

#pragma unroll
        for (int kk = 0; kk < BKt; kk++) {
            ulonglong2 aA = *(const ulonglong2*)&As[buf][kk * ASTR + r0];
            ulonglong2 aB = *(const ulonglong2*)&As[buf][kk * ASTR + r0 + 4];
            ulonglong2 bq0 = *(const ulonglong2*)&Bs[buf][kk * BSTRU + cb];
            ulonglong2 bq1 = *(const ulonglong2*)&Bs[buf][kk * BSTRU + cb + 16];
            ulonglong2 bq2 = *(const ulonglong2*)&Bs[buf][kk * BSTRU + cb + 32];
            ulonglong2 bq3 = *(const ulonglong2*)&Bs[buf][kk * BSTRU + cb + 48];
            ffma2(acc[0][0], aA.x, bq0.x); ffma2(acc[0][1], aA.x, bq0.y);
            ffma2(acc[1][0], aA.y, bq0.x); ffma2(acc[1][1], aA.y, bq0.y);
            ffma2(acc[2][0], aB.x, bq0.x); ffma2(acc[2][1], aB.x, bq0.y);
            ffma2(acc[3][0], aB.y, bq0.x); ffma2(acc[3][1], aB.y, bq0.y);
            ffma2(acc[0][2], aA.x, bq1.x); ffma2(acc[0][3], aA.x, bq1.y);
            ffma2(acc[1][2], aA.y, bq1.x); ffma2(acc[1][3], aA.y, bq1.y);
            ffma2(acc[2][2], aB.x, bq1.x); ffma2(acc[2][3], aB.x, bq1.y);
            ffma2(acc[3][2], aB.y, bq1.x); ffma2(acc[3][3], aB.y, bq1.y);
            ffma2(acc[0][4], aA.x, bq2.x); ffma2(acc[0][5], aA.x, bq2.y);
            ffma2(acc[1][4], aA.y, bq2.x); ffma2(acc[1][5], aA.y, bq2.y);
            ffma2(acc[2][4], aB.x, bq2.x); ffma2(acc[2][5], aB.x, bq2.y);
            ffma2(acc[3][4], aB.y, bq2.x); ffma2(acc[3][5], aB.y, bq2.y);
            ffma2(acc[0][6], aA.x, bq3.x); ffma2(acc[0][7], aA.x, bq3.y);
            ffma2(acc[1][6], aA.y, bq3.x); ffma2(acc[1][7], aA.y, bq3.y);
            ffma2(acc[2][6], aB.x, bq3.x); ffma2(acc[2][7], aB.x, bq3.y);
            ffma2(acc[3][6], aB.y, bq3.x); ffma2(acc[3][7], aB.y, bq3.y);
        }

        if (more) {
            const int nb = buf ^ 1;
            *(float4*)&As[nb][kload * ASTR + mld]     = a0v;
            *(float4*)&As[nb][kload * ASTR + mld + 4] = a1v;
            Bs[nb][(bk + 0) * BSTRU + bc] = pack2(b0v.x, b0v.x);
            Bs[nb][(bk + 1) * BSTRU + bc] = pack2(b0v.y, b0v.y);
            Bs[nb][(bk + 2) * BSTRU + bc] = pack2(b0v.z, b0v.z);
            Bs[nb][(bk + 3) * BSTRU + bc] = pack2(b0v.w, b0v.w);
            Bs[nb][(bk + 4) * BSTRU + bc] = pack2(b1v.x, b1v.x);
            Bs[nb][(bk + 5) * BSTRU + bc] = pack2(b1v.y, b1v.y);
            Bs[nb][(bk + 6) * BSTRU + bc] = pack2(b1v.z, b1v.z);
            Bs[nb][(bk + 7) * BSTRU + bc] = pack2(b1v.w, b1v.w);
        }
        __syncthreads();
        buf ^= 1;
    }

    float* zbase = g_zp + (size_t)blockIdx.y * CHUNK * B_ROWS;
#pragma unroll
    for (int p = 0; p < 4; p++) {
#pragma unroll
        for (int j = 0; j < 4; j++) {
#pragma unroll
            for (int h = 0; h < 2; h++) {
                const int c = cb + 16 * j + h;
                *(u64*)(zbase + (size_t)c * B_ROWS + brow + r0 + 2 * p) =
                    acc[p][2 * j + h];
            }
        }
    }
}

// ---------------------------------------------------------------------------
// Triangular epilogue v4: warp-specialized pipeline, FULLY UNROLLED rounds
// (register arrays stay static -> no local spill), right-looking serial phase:
// after each sigmoid, scatter-update future acc16 (independent FMAs); the
// critical chain per node is sig5 -> one fmaf (~45 cyc) instead of a dependent
// 8-deep dot (~100 cyc).
// ---------------------------------------------------------------------------
__global__ __launch_bounds__(256) void epi_chunk(const float* __restrict__ W,
                                                 const float* __restrict__ bias,
                                                 int i0)
{
    __shared__ u64   o_sm[64 * 32];        // [node pair][lane], 16 KB
    __shared__ float Wt[8][16][16];        // per-warp serial W tile, 4 KB

    const int P    = N_IN + i0;
    const int tid  = threadIdx.x;
    const int w    = tid >> 5;
    const int lane = tid & 31;
    const int m    = blockIdx.x * 32 + lane;
    const int nb   = 16 * w;

    // ---- stage this warp's 16x16 serial W tile into smem (off crit path)
#pragma unroll
    for (int i = lane; i < 64; i += 32) {
        const int row = i >> 2, c4 = i & 3;
        float4 v = *(const float4*)&W[(size_t)(i0 + nb + row) * N_NODES + P + nb + 4 * c4];
        *(float4*)&Wt[w][row][4 * c4] = v;
    }
    // ---- prefetch dense W tiles this warp will need (rounds 1..w) to L2
    {
        const int row = lane & 15, half = lane >> 4;
#pragma unroll 1
        for (int j = 0; j < w; j++) {
            const float* pf = &W[(size_t)(i0 + nb + row) * N_NODES + P + 16 * j + 8 * half];
            asm volatile("prefetch.global.L2 [%0];" :: "l"(pf));
        }
    }
    __syncwarp();

    // ---- fold GEMM k-split partials + bias into register acc
    float acc16[16];
#pragma unroll
    for (int n = 0; n < 16; n++) {
        float v = bias[i0 + nb + n];
#pragma unroll
        for (int s = 0; s < KSPLIT; s++)
            v += g_zp[((size_t)s * CHUNK + nb + n) * B_ROWS + m];
        acc16[n] = v;
    }

    // ---- pipelined rounds (fully unrolled; all array indices static)
#pragma unroll
    for (int j = 0; j < 8; j++) {
        if (j > 0) {
            __syncthreads();
            if (w >= j) {
                u64 o8[8];
#pragma unroll
                for (int t = 0; t < 8; t++)
                    o8[t] = o_sm[(8 * (j - 1) + t) * 32 + lane];
#pragma unroll
                for (int n = 0; n < 16; n++) {
                    const float* wr = W + (size_t)(i0 + nb + n) * N_NODES + P + 16 * (j - 1);
                    ulonglong2 w01 = *(const ulonglong2*)wr;
                    ulonglong2 w23 = *(const ulonglong2*)(wr + 4);
                    ulonglong2 w45 = *(const ulonglong2*)(wr + 8);
                    ulonglong2 w67 = *(const ulonglong2*)(wr + 12);
                    u64 zp = 0ULL;
                    ffma2(zp, w01.x, o8[0]); ffma2(zp, w01.y, o8[1]);
                    ffma2(zp, w23.x, o8[2]); ffma2(zp, w23.y, o8[3]);
                    ffma2(zp, w45.x, o8[4]); ffma2(zp, w45.y, o8[5]);
                    ffma2(zp, w67.x, o8[6]); ffma2(zp, w67.y, o8[7]);
                    float2 f = unpack2(zp);
                    acc16[n] += f.x + f.y;
                }
            }
        }
        if (w == j) {
            // right-looking serial phase: sigmoid then scatter-update
            float o_loc[16];
#pragma unroll
            for (int cc = 0; cc < 16; cc++) {
                float o = sig5(acc16[cc]);
                o_loc[cc] = o;
#pragma unroll
                for (int n = cc + 1; n < 16; n++)
                    acc16[n] = fmaf(Wt[w][n][cc], o, acc16[n]);
            }
            // publish outputs: o pairs to smem for later rounds, scalars to gmem
#pragma unroll
            for (int t = 0; t < 8; t++)
                o_sm[(8 * w + t) * 32 + lane] = pack2(o_loc[2 * t], o_loc[2 * t + 1]);
#pragma unroll
            for (int cc = 0; cc < 16; cc++)
                g_out_T[(size_t)(P + nb + cc) * B_ROWS + m] = o_loc[cc];
        }
    }
}

// ---------------------------------------------------------------------------
// Transpose kernels (32x32 smem tiles)
// ---------------------------------------------------------------------------
__global__ void init_T(const float* __restrict__ x)
{
    __shared__ float t[32][33];
    const int rb = blockIdx.x * 32;
    const int cb = blockIdx.y * 32;
    const int tx = threadIdx.x, ty = threadIdx.y;
#pragma unroll
    for (int j = 0; j < 4; j++)
        t[ty + 8 * j][tx] = x[(size_t)(rb + ty + 8 * j) * N_IN + cb + tx];
    __syncthreads();
#pragma unroll
    for (int j = 0; j < 4; j++)
        g_out_T[(size_t)(cb + ty + 8 * j) * B_ROWS + rb + tx] = t[tx][ty + 8 * j];
}

__global__ void copy_T(float* __restrict__ out)
{
    __shared__ float t[32][33];
    const int rb = blockIdx.x * 32;
    const int cb = blockIdx.y * 32;
    const int tx = threadIdx.x, ty = threadIdx.y;
#pragma unroll
    for (int j = 0; j < 4; j++)
        t[ty + 8 * j][tx] = g_out_T[(size_t)(N_NODES - N_OUT + cb + ty + 8 * j) * B_ROWS
                                    + rb + tx];
    __syncthreads();
#pragma unroll
    for (int j = 0; j < 4; j++)
        out[(size_t)(rb + ty + 8 * j) * N_OUT + cb + tx] = t[tx][ty + 8 * j];
}

// ---------------------------------------------------------------------------
extern "C" void kernel_launch(void* const* d_in, const int* in_sizes, int n_in,
                              void* d_out, int out_size)
{
    (void)in_sizes; (void)n_in; (void)out_size;
    const float* x  = (const float*)d_in[0];
    const float* W  = (const float*)d_in[1];
    const float* b  = (const float*)d_in[2];
    float* out = (float*)d_out;

    dim3 tblk(32, 8);
    init_T<<<dim3(B_ROWS / 32, N_IN / 32), tblk>>>(x);
    for (int k = 0; k < NCHUNK; k++) {
        gemm_chunk<<<dim3(B_ROWS / BM, KSPLIT), 256>>>(W, k * CHUNK);
        epi_chunk<<<B_ROWS / 32, 256>>>(W, b, k * CHUNK);
    }
    copy_T<<<dim3(B_ROWS / 32, N_OUT / 32), tblk>>>(out);
}